// round 17
// baseline (speedup 1.0000x reference)
#include <cuda_runtime.h>
#include <cuda_bf16.h>

#define STEPS 16

// ---- lifted-rotation coefficient tables (layout identical to R15/R16) -----
// Scaled coords: x_true = d ∘ x̂ ; per pair (a,b):
//   â' = â − β·b̂ ;  b̂' = α·â + b̂            (8 FMA, β/α complex)
//   β = (st/ct)·(d_b/d_a), α = (st/ct)·(d_a/d_b)
// gE/gO[s][c][j][L] = (βr, βi, αr, αi); boundary coeffs packed:
// gOB[s][c][L] = { β of pair 128c+4L+3 , α of pair 128c+4L-1 }.
// Nonexistent pairs -> zeros. g_om[e] = ω_e · d_e(final).
__device__ float4 gE [STEPS][4][4][32];
__device__ float4 gO [STEPS][4][3][32];
__device__ __align__(16) float2 gOB[STEPS][4][32][2];
__device__ float2 g_om[1024];

__device__ __forceinline__ float safe_ct(float ct) {
    float a = fabsf(ct);
    return (a < 1e-30f) ? copysignf(1e-30f, ct) : ct;
}

// emit (beta|alpha) from tangent tv, unit ratio R = d_b/d_a phase, D = lg_b - lg_a
__device__ __forceinline__ float4 emit_C(float tv, float Rr, float Ri, float D) {
    float m  = __expf(D);
    float mi = __expf(-D);
    return make_float4(tv * m * Rr, tv * m * Ri, tv * mi * Rr, -tv * mi * Ri);
}

// ---- SINGLE precompute kernel: one thread per table row, zero dependencies.
// Each thread recomputes its own d-ratio prefix (O(s) redundant transcendental
// work, fully parallel). Role conventions match the verified R16 walk:
//   even sweep t, pair p: a = 2p gets sgn(ct_et)*(sp_ep + i cp_ep), b = 2p+1
//   gets sgn(ct_et); both lg += log|ct_et|.
//   odd sweep t, pair q: a = 2q+1 gets sgn(ct_ot)*(sp_op + i cp_op),
//   b = 2q+2 gets sgn(ct_ot); both lg += log|ct_ot|. e = 0,1023 identity.
__global__ void eunn_pre(const float* __restrict__ omega,
                         const float* __restrict__ et,
                         const float* __restrict__ ot,
                         const float* __restrict__ ep,
                         const float* __restrict__ op)
{
    int idx = blockIdx.x * blockDim.x + threadIdx.x;

    if (idx < 8192) {
        // ===== even-pair entry (s, p): a = 2p, b = 2p+1; state BEFORE sweep 2s
        int s = idx >> 9, p = idx & 511;
        float Rr = 1.f, Ri = 0.f, D = 0.f;
        for (int t = 0; t < s; t++) {
            // even sweep t: ratio *= conj(w_ep) = (sp - i*cp); logs cancel
            float sp, cp; __sincosf(ep[t * 512 + p], &sp, &cp);
            float nr = Rr * sp + Ri * cp;
            float ni = Ri * sp - Rr * cp;
            Rr = nr; Ri = ni;
            // odd sweep t: a in pair p-1 (b-role), b in pair p (a-role)
            float sgn = 1.f;
            if (p > 0) {
                float c1 = safe_ct(__cosf(ot[t * 511 + (p - 1)]));
                D -= __logf(fabsf(c1));
                if (c1 < 0.f) sgn = -sgn;
            }
            if (p < 511) {
                float c2 = safe_ct(__cosf(ot[t * 511 + p]));
                D += __logf(fabsf(c2));
                if (c2 < 0.f) sgn = -sgn;
                float so, co; __sincosf(op[t * 511 + p], &so, &co);
                // ratio *= sgn*(so + i*co)
                float mr = Rr * so - Ri * co;
                float mi = Rr * co + Ri * so;
                Rr = sgn * mr; Ri = sgn * mi;
            } else {
                Rr = sgn * Rr; Ri = sgn * Ri;
            }
        }
        float st_, ct_; __sincosf(et[s * 512 + p], &st_, &ct_);
        float tv = st_ / safe_ct(ct_);
        int c = p >> 7, L = (p & 127) >> 2, jj = p & 3;
        gE[s][c][jj][L] = emit_C(tv, Rr, Ri, D);

    } else if (idx < 16384) {
        // ===== odd-pair entry (s, q): a = 2q+1, b = 2q+2; state AFTER even s
        int s = (idx - 8192) >> 9, q = idx & 511;
        if (q == 511) {
            // nonexistent boundary pairs for this step: exact identity (zeros)
            gOB[s][3][31][0] = make_float2(0.f, 0.f);
            gOB[s][0][0][1]  = make_float2(0.f, 0.f);
            return;
        }
        float Rr = 1.f, Ri = 0.f, D = 0.f;
        for (int t = 0; t <= s; t++) {
            // even sweep t: a b-role in pair q, b a-role in pair q+1
            float c1 = safe_ct(__cosf(et[t * 512 + q]));
            float c2 = safe_ct(__cosf(et[t * 512 + (q + 1)]));
            D += __logf(fabsf(c2)) - __logf(fabsf(c1));
            float sgn = 1.f;
            if (c1 < 0.f) sgn = -sgn;
            if (c2 < 0.f) sgn = -sgn;
            float sp, cp; __sincosf(ep[t * 512 + (q + 1)], &sp, &cp);
            // ratio *= sgn*(sp + i*cp)
            float nr = Rr * sp - Ri * cp;
            float ni = Rr * cp + Ri * sp;
            Rr = sgn * nr; Ri = sgn * ni;
            // odd sweep t (only for t < s): both in pair q -> conj(w_op)
            if (t < s) {
                float so, co; __sincosf(op[t * 511 + q], &so, &co);
                float mr = Rr * so + Ri * co;
                float mi = Ri * so - Rr * co;
                Rr = mr; Ri = mi;
            }
        }
        float st_, ct_; __sincosf(ot[s * 511 + q], &st_, &ct_);
        float tv = st_ / safe_ct(ct_);
        float4 C = emit_C(tv, Rr, Ri, D);
        int c = q >> 7, L = (q & 127) >> 2, jj = q & 3;
        if (jj < 3) {
            gO[s][c][jj][L] = C;
        } else {
            gOB[s][c][L][0] = make_float2(C.x, C.y);                     // beta
            int q1 = q + 1;
            gOB[s][q1 >> 7][(q1 & 127) >> 2][1] = make_float2(C.z, C.w); // alpha
        }

    } else if (idx < 17408) {
        // ===== omega entry e: full 32-sweep d walk (verified R16 form) =====
        int e = idx - 16384;
        float phr = 1.f, phi = 0.f, lg = 0.f;
        for (int s = 0; s < STEPS; s++) {
            {   // even sweep: pair p = e>>1, a-role if e even
                int p = e >> 1;
                float ct = safe_ct(__cosf(et[s * 512 + p]));
                lg += __logf(fabsf(ct));
                float sgn = (ct < 0.f) ? -1.f : 1.f;
                if ((e & 1) == 0) {
                    float sp, cp; __sincosf(ep[s * 512 + p], &sp, &cp);
                    float nr = sp * phr - cp * phi;
                    float ni = sp * phi + cp * phr;
                    phr = sgn * nr; phi = sgn * ni;
                } else {
                    phr *= sgn; phi *= sgn;
                }
            }
            if (e != 0 && e != 1023) {  // odd sweep
                int q; bool arole;
                if (e & 1) { q = (e - 1) >> 1; arole = true;  }
                else       { q = (e >> 1) - 1; arole = false; }
                float ct = safe_ct(__cosf(ot[s * 511 + q]));
                lg += __logf(fabsf(ct));
                float sgn = (ct < 0.f) ? -1.f : 1.f;
                if (arole) {
                    float sp, cp; __sincosf(op[s * 511 + q], &sp, &cp);
                    float nr = sp * phr - cp * phi;
                    float ni = sp * phi + cp * phr;
                    phr = sgn * nr; phi = sgn * ni;
                } else {
                    phr *= sgn; phi *= sgn;
                }
            }
        }
        float sn, cs; __sincosf(omega[e], &sn, &cs);
        float sc = __expf(lg);
        g_om[e] = make_float2(sc * (cs * phr - sn * phi),
                              sc * (cs * phi + sn * phr));
    }
}

// 8-FMA lifted rotation; C = (br, bi, ar, ai) meaning beta, alpha
#define LROT(Ar, Ai, Br, Bi, C)                                        \
    do {                                                               \
        float _ar = (Ar), _ai = (Ai), _br = (Br), _bi = (Bi);          \
        (Ar) = fmaf(-(C).x, _br, fmaf( (C).y, _bi, _ar));              \
        (Ai) = fmaf(-(C).x, _bi, fmaf(-(C).y, _br, _ai));              \
        (Br) = fmaf( (C).z, _ar, fmaf(-(C).w, _ai, _br));              \
        (Bi) = fmaf( (C).z, _ai, fmaf( (C).w, _ar, _bi));              \
    } while (0)

// 16-step scan for R rows (identical to R15/R16's, which passed)
template<int R>
__device__ __forceinline__ void eunn_steps(
    float (&xr)[4][8], float (&xi)[4][8],
    float (&sE0)[2][2][4][4][2], float (&sE7)[2][2][4][4][2],
    int lane, int c, int g)
{
    float4 E0 = gE[0][c][0][lane], E1 = gE[0][c][1][lane];
    float4 E2 = gE[0][c][2][lane], E3 = gE[0][c][3][lane];

#pragma unroll 1
    for (int s = 0; s < STEPS; s++) {
        int par = s & 1;

        float4 O0 = gO[s][c][0][lane], O1 = gO[s][c][1][lane];
        float4 O2 = gO[s][c][2][lane];
        float4 OB = *(const float4*)&gOB[s][c][lane][0];   // (beta3 | alphaL)

        // ---------------- even sweep: 4 lane-internal pairs ----------------
#pragma unroll
        for (int r = 0; r < R; r++) {
            LROT(xr[r][0], xi[r][0], xr[r][1], xi[r][1], E0);
            LROT(xr[r][2], xi[r][2], xr[r][3], xi[r][3], E1);
            LROT(xr[r][4], xi[r][4], xr[r][5], xi[r][5], E2);
            LROT(xr[r][6], xi[r][6], xr[r][7], xi[r][7], E3);
        }

        // publish post-even slice edges
        if (lane == 0) {
#pragma unroll
            for (int r = 0; r < R; r++) {
                sE0[par][g][c][r][0] = xr[r][0];
                sE0[par][g][c][r][1] = xi[r][0];
            }
        }
        if (lane == 31) {
#pragma unroll
            for (int r = 0; r < R; r++) {
                sE7[par][g][c][r][0] = xr[r][7];
                sE7[par][g][c][r][1] = xi[r][7];
            }
        }
        asm volatile("bar.sync %0, 128;" :: "r"(g + 1) : "memory");

        // prefetch NEXT step's even coefficients (hidden under odd sweep)
        int sn = (s + 1 < STEPS) ? s + 1 : s;
        E0 = gE[sn][c][0][lane]; E1 = gE[sn][c][1][lane];
        E2 = gE[sn][c][2][lane]; E3 = gE[sn][c][3][lane];

        // ---------------- odd sweep ----------------
        bool smR = (lane == 31) && (c < 3);
        bool smL = (lane == 0)  && (c > 0);
#pragma unroll
        for (int r = 0; r < R; r++) {
            // neighbor pre-odd edges: right e0, left e7
            float nbr = __shfl_down_sync(0xffffffffu, xr[r][0], 1);
            float nbi = __shfl_down_sync(0xffffffffu, xi[r][0], 1);
            float lar = __shfl_up_sync  (0xffffffffu, xr[r][7], 1);
            float lai = __shfl_up_sync  (0xffffffffu, xi[r][7], 1);
            if (smR) { nbr = sE0[par][g][c + 1][r][0]; nbi = sE0[par][g][c + 1][r][1]; }
            if (smL) { lar = sE7[par][g][c - 1][r][0]; lai = sE7[par][g][c - 1][r][1]; }

            // internal pairs — fill shuffle latency
            LROT(xr[r][1], xi[r][1], xr[r][2], xi[r][2], O0);
            LROT(xr[r][3], xi[r][3], xr[r][4], xi[r][4], O1);
            LROT(xr[r][5], xi[r][5], xr[r][6], xi[r][6], O2);

            // boundary a'-half: e7' = e7 − beta * (right neighbor pre-odd e0)
            xr[r][7] = fmaf(-OB.x, nbr, fmaf( OB.y, nbi, xr[r][7]));
            xi[r][7] = fmaf(-OB.x, nbi, fmaf(-OB.y, nbr, xi[r][7]));

            // boundary b'-half: e0' = e0 + alpha * (left neighbor pre-odd e7)
            xr[r][0] = fmaf(OB.z, lar, fmaf(-OB.w, lai, xr[r][0]));
            xi[r][0] = fmaf(OB.z, lai, fmaf( OB.w, lar, xi[r][0]));
        }
    }
}

// One single wave: 296 CTAs; each g-group (4 slice-warps) owns 7 rows
// (last 48 groups: 6): batch A = 4 rows then batch B = 3 (or 2, masked).
__global__ void __launch_bounds__(256, 2)
eunn_main(const float* __restrict__ x, float* __restrict__ out)
{
    __shared__ float sE0[2][2][4][4][2];   // [parity][g][slice][row][re/im]
    __shared__ float sE7[2][2][4][4][2];

    int lane  = threadIdx.x & 31;
    int wblk  = threadIdx.x >> 5;
    int c     = wblk & 3;
    int g     = wblk >> 2;
    int ebase = c * 256 + lane * 8;

    int gid = blockIdx.x * 2 + g;          // 0..591
    int row0, nB;
    if (gid < 544) { row0 = gid * 7;                  nB = 3; }
    else           { row0 = 3808 + (gid - 544) * 6;   nB = 2; }

    const float4* omv = (const float4*)g_om;
    float xr[4][8], xi[4][8];

    // =========================== batch A: 4 rows ===========================
#pragma unroll
    for (int r = 0; r < 4; r++) {
        const float4* p4 = (const float4*)(x + (size_t)(row0 + r) * 2048 + ebase * 2);
#pragma unroll
        for (int i = 0; i < 4; i++) {
            float4 v = __ldg(&p4[i]);
            xr[r][2*i] = v.x; xi[r][2*i] = v.y; xr[r][2*i+1] = v.z; xi[r][2*i+1] = v.w;
        }
    }

    eunn_steps<4>(xr, xi, sE0, sE7, lane, c, g);

#pragma unroll
    for (int r = 0; r < 4; r++) {
        float4* o4 = (float4*)(out + (size_t)(row0 + r) * 2048 + ebase * 2);
#pragma unroll
        for (int i = 0; i < 4; i++) {
            float4 m = omv[(ebase >> 1) + i];
            float r0 = xr[r][2*i]   * m.x - xi[r][2*i]   * m.y;
            float i0 = xr[r][2*i]   * m.y + xi[r][2*i]   * m.x;
            float r1 = xr[r][2*i+1] * m.z - xi[r][2*i+1] * m.w;
            float i1 = xr[r][2*i+1] * m.w + xi[r][2*i+1] * m.z;
            o4[i] = make_float4(r0, i0, r1, i1);
        }
    }

    // ========================= batch B: nB (2-3) rows ======================
    int rowB = row0 + 4;
#pragma unroll
    for (int r = 0; r < 3; r++) {
        int rr = rowB + (r < nB ? r : nB - 1);   // clamp: duplicate last valid row
        const float4* p4 = (const float4*)(x + (size_t)rr * 2048 + ebase * 2);
#pragma unroll
        for (int i = 0; i < 4; i++) {
            float4 v = __ldg(&p4[i]);
            xr[r][2*i] = v.x; xi[r][2*i] = v.y; xr[r][2*i+1] = v.z; xi[r][2*i+1] = v.w;
        }
    }

    eunn_steps<3>(xr, xi, sE0, sE7, lane, c, g);

#pragma unroll
    for (int r = 0; r < 3; r++) {
        if (r < nB) {
            float4* o4 = (float4*)(out + (size_t)(rowB + r) * 2048 + ebase * 2);
#pragma unroll
            for (int i = 0; i < 4; i++) {
                float4 m = omv[(ebase >> 1) + i];
                float r0 = xr[r][2*i]   * m.x - xi[r][2*i]   * m.y;
                float i0 = xr[r][2*i]   * m.y + xi[r][2*i]   * m.x;
                float r1 = xr[r][2*i+1] * m.z - xi[r][2*i+1] * m.w;
                float i1 = xr[r][2*i+1] * m.w + xi[r][2*i+1] * m.z;
                o4[i] = make_float4(r0, i0, r1, i1);
            }
        }
    }
}

extern "C" void kernel_launch(void* const* d_in, const int* in_sizes, int n_in,
                              void* d_out, int out_size)
{
    const float* x     = (const float*)d_in[0];
    const float* omega = (const float*)d_in[1];
    const float* et    = (const float*)d_in[2];
    const float* ot    = (const float*)d_in[3];
    const float* ep    = (const float*)d_in[4];
    const float* op    = (const float*)d_in[5];

    eunn_pre<<<68, 256>>>(omega, et, ot, ep, op);    // ONE dependency-free precompute
    eunn_main<<<296, 256>>>(x, (float*)d_out);       // single wave
}